// round 15
// baseline (speedup 1.0000x reference)
#include <cuda_runtime.h>

#define C_CH   256
#define K_KERN 4
#define HID    64
#define HW     4096
#define B_MAX  32

__device__ float g_gap[B_MAX * C_CH];
__device__ float g_attn[B_MAX * K_KERN];

// ---------------------------------------------------------------------------
// Kernel 1: global average pool, TWO (b,c) planes per block (8 front-batched
// LDG.128 per thread -> 2x MLP vs 1-plane version).
// ---------------------------------------------------------------------------
__global__ void __launch_bounds__(256) gap_kernel(const float* __restrict__ x) {
    const int bc0 = blockIdx.x * 2;
    const float4* __restrict__ p0 = (const float4*)(x + (size_t)bc0 * HW);
    const float4* __restrict__ p1 = (const float4*)(x + (size_t)(bc0 + 1) * HW);
    float4 v0[4], v1[4];
#pragma unroll
    for (int i = 0; i < 4; i++) v0[i] = __ldg(&p0[threadIdx.x + i * 256]);
#pragma unroll
    for (int i = 0; i < 4; i++) v1[i] = __ldg(&p1[threadIdx.x + i * 256]);

    float s0 = 0.f, s1 = 0.f;
#pragma unroll
    for (int i = 0; i < 4; i++) {
        s0 += (v0[i].x + v0[i].y) + (v0[i].z + v0[i].w);
        s1 += (v1[i].x + v1[i].y) + (v1[i].z + v1[i].w);
    }
#pragma unroll
    for (int o = 16; o > 0; o >>= 1) {
        s0 += __shfl_down_sync(0xffffffffu, s0, o);
        s1 += __shfl_down_sync(0xffffffffu, s1, o);
    }
    __shared__ float ws0[8], ws1[8];
    const int lane = threadIdx.x & 31, w = threadIdx.x >> 5;
    if (lane == 0) { ws0[w] = s0; ws1[w] = s1; }
    __syncthreads();
    if (threadIdx.x == 0) {
        float t0 = 0.f, t1 = 0.f;
#pragma unroll
        for (int i = 0; i < 8; i++) { t0 += ws0[i]; t1 += ws1[i]; }
        g_gap[bc0]     = t0 * (1.0f / (float)HW);
        g_gap[bc0 + 1] = t1 * (1.0f / (float)HW);
    }
}

// ---------------------------------------------------------------------------
// Kernel 2: fc1 -> relu -> fc2 -> softmax. One block per batch. (unchanged)
// ---------------------------------------------------------------------------
__global__ void __launch_bounds__(256) attn_kernel(const float* __restrict__ fc1_w,
                                                   const float* __restrict__ fc1_b,
                                                   const float* __restrict__ fc2_w,
                                                   const float* __restrict__ fc2_b) {
    const int b = blockIdx.x;
    __shared__ float g[C_CH];
    __shared__ float h[HID];
    __shared__ float lg[K_KERN];

    g[threadIdx.x] = g_gap[b * C_CH + threadIdx.x];
    __syncthreads();

    if (threadIdx.x < HID) {
        const float* __restrict__ wr = fc1_w + threadIdx.x * C_CH;
        float acc = fc1_b[threadIdx.x];
#pragma unroll 8
        for (int c = 0; c < C_CH; c++) acc = fmaf(g[c], wr[c], acc);
        h[threadIdx.x] = fmaxf(acc, 0.f);
    }
    __syncthreads();

    if (threadIdx.x < K_KERN) {
        const float* __restrict__ wr = fc2_w + threadIdx.x * HID;
        float acc = fc2_b[threadIdx.x];
#pragma unroll 8
        for (int j = 0; j < HID; j++) acc = fmaf(h[j], wr[j], acc);
        lg[threadIdx.x] = acc;
    }
    __syncthreads();

    if (threadIdx.x == 0) {
        float m = lg[0];
#pragma unroll
        for (int k = 1; k < K_KERN; k++) m = fmaxf(m, lg[k]);
        float e[K_KERN], s = 0.f;
#pragma unroll
        for (int k = 0; k < K_KERN; k++) { e[k] = expf(lg[k] - m); s += e[k]; }
        const float inv = 1.0f / s;
#pragma unroll
        for (int k = 0; k < K_KERN; k++) g_attn[b * K_KERN + k] = e[k] * inv;
    }
}

// ---------------------------------------------------------------------------
// Kernel 3: depthwise 3x3, effective filter w_eff = sum_k attn[b,k]*w[k,c].
// Strip = 32 rows per half-warp: read amplification 34/32 = 1.0625x.
// 16 half-warps per 256-thread block -> 8 planes per block, 1024 blocks.
// No smem / no syncthreads; width-16 shuffle halo; evict-first stores.
// ---------------------------------------------------------------------------
__device__ __forceinline__ void load_row6(const float4* __restrict__ xp,
                                          int row, int sub, float* d) {
    float4 v;
    if ((unsigned)row < 64u) v = __ldg(&xp[row * 16 + sub]);
    else                     v = make_float4(0.f, 0.f, 0.f, 0.f);
    float l = __shfl_up_sync(0xffffffffu, v.w, 1, 16);
    float r = __shfl_down_sync(0xffffffffu, v.x, 1, 16);
    if (sub == 0)  l = 0.f;
    if (sub == 15) r = 0.f;
    d[0] = l; d[1] = v.x; d[2] = v.y; d[3] = v.z; d[4] = v.w; d[5] = r;
}

__global__ void __launch_bounds__(256) conv_kernel(const float* __restrict__ x,
                                                   const float* __restrict__ conv_w,
                                                   float* __restrict__ out) {
    const int tid  = threadIdx.x;
    const int lane = tid & 31;
    const int warp = tid >> 5;
    const int sub  = lane & 15;              // column group (0..15)
    const int gs   = warp * 2 + (lane >> 4); // half-warp id 0..15
    const int plane_local = gs >> 1;         // 0..7
    const int strip = gs & 1;                // 0..1 -> rows [strip*32, +32)

    const int grp = gridDim.x - 1 - blockIdx.x;   // reversed order
    const int bc = grp * 8 + plane_local;
    const int b = bc >> 8;
    const int c = bc & 255;

    const float a0 = g_attn[b * 4 + 0];
    const float a1 = g_attn[b * 4 + 1];
    const float a2 = g_attn[b * 4 + 2];
    const float a3 = g_attn[b * 4 + 3];
    float w[9];
    const float* __restrict__ w0 = conv_w + (size_t)0 * C_CH * 9 + c * 9;
    const float* __restrict__ w1 = conv_w + (size_t)1 * C_CH * 9 + c * 9;
    const float* __restrict__ w2 = conv_w + (size_t)2 * C_CH * 9 + c * 9;
    const float* __restrict__ w3 = conv_w + (size_t)3 * C_CH * 9 + c * 9;
#pragma unroll
    for (int i = 0; i < 9; i++)
        w[i] = fmaf(a0, __ldg(&w0[i]),
               fmaf(a1, __ldg(&w1[i]),
               fmaf(a2, __ldg(&w2[i]), a3 * __ldg(&w3[i]))));

    const float4* __restrict__ xp = (const float4*)(x + (size_t)bc * HW);
    float4* __restrict__ op = (float4*)(out + (size_t)bc * HW);

    const int rbase = strip * 32;

    float rb[3][6];
    load_row6(xp, rbase - 1, sub, rb[0]);
    load_row6(xp, rbase,     sub, rb[1]);

#pragma unroll
    for (int rr = 0; rr < 32; rr++) {
        const int i0 = rr % 3;
        const int i1 = (rr + 1) % 3;
        const int i2 = (rr + 2) % 3;
        load_row6(xp, rbase + rr + 1, sub, rb[i2]);

        float4 o;
        float* ov = (float*)&o;
#pragma unroll
        for (int i = 0; i < 4; i++) {
            float acc;
            acc = rb[i0][i]     * w[0];
            acc = fmaf(rb[i0][i + 1], w[1], acc);
            acc = fmaf(rb[i0][i + 2], w[2], acc);
            acc = fmaf(rb[i1][i],     w[3], acc);
            acc = fmaf(rb[i1][i + 1], w[4], acc);
            acc = fmaf(rb[i1][i + 2], w[5], acc);
            acc = fmaf(rb[i2][i],     w[6], acc);
            acc = fmaf(rb[i2][i + 1], w[7], acc);
            acc = fmaf(rb[i2][i + 2], w[8], acc);
            ov[i] = acc;
        }
        __stcs(&op[(rbase + rr) * 16 + sub], o);
    }
}

// ---------------------------------------------------------------------------
extern "C" void kernel_launch(void* const* d_in, const int* in_sizes, int n_in,
                              void* d_out, int out_size) {
    const float* x      = (const float*)d_in[0];
    const float* conv_w = (const float*)d_in[1];
    const float* fc1_w  = (const float*)d_in[2];
    const float* fc1_b  = (const float*)d_in[3];
    const float* fc2_w  = (const float*)d_in[4];
    const float* fc2_b  = (const float*)d_in[5];
    float* out = (float*)d_out;

    const int B = in_sizes[0] / (C_CH * HW);   // 32

    gap_kernel<<<B * C_CH / 2, 256>>>(x);
    attn_kernel<<<B, 256>>>(fc1_w, fc1_b, fc2_w, fc2_b);
    conv_kernel<<<B * C_CH / 8, 256>>>(x, conv_w, out);
}